// round 1
// baseline (speedup 1.0000x reference)
#include <cuda_runtime.h>
#include <cstdint>

#define B_ 4
#define S_ 2048
#define D_ 1024
#define H_ 16
#define A_ 64
#define PADW 68   // floats per padded row: keeps float4 alignment, staggers banks

// Scratch: projected q/k/v heads, [3][B][H][S][A] fp32 (~100 MB, static => allocation-guard safe)
__device__ float g_ph[3][(size_t)B_ * H_ * S_ * A_];

// ---------------------------------------------------------------------------
// Projection kernel: out[b,h,s,a] = sum_d x[b,s,d] * W[h,d,a] + bias[h,a]
// Grid: (S/64, B*H, 3), block 256. 64x64 output tile, K-chunks of 16.
// ---------------------------------------------------------------------------
__global__ __launch_bounds__(256) void proj_kernel(
    const float* __restrict__ q, const float* __restrict__ k, const float* __restrict__ v,
    const float* __restrict__ Wq, const float* __restrict__ bq,
    const float* __restrict__ Wk, const float* __restrict__ bk,
    const float* __restrict__ Wv, const float* __restrict__ bv)
{
    const int tid = threadIdx.x;
    const int stile = blockIdx.x;
    const int bh = blockIdx.y;
    const int b = bh / H_, h = bh % H_;
    const int z = blockIdx.z;

    const float* x    = (z == 0) ? q  : (z == 1) ? k  : v;
    const float* W    = (z == 0) ? Wq : (z == 1) ? Wk : Wv;
    const float* bias = (z == 0) ? bq : (z == 1) ? bk : bv;
    float* out = g_ph[z];

    __shared__ float Xs[16][PADW];  // k-major: Xs[d][s]
    __shared__ float Ws[16][PADW];  // Ws[d][a]

    const int ty = tid >> 4;        // 0..15 -> q-row group
    const int tx = tid & 15;        // 0..15 -> a-col group
    const int s0 = stile * 64;

    // loader indices
    const int lrow = tid >> 2;          // 0..63 (s within tile)
    const int lc4  = (tid & 3) << 2;    // 0,4,8,12 (d within chunk)
    const int wdd  = tid >> 4;          // 0..15 (d within chunk)
    const int wa0  = (tid & 15) << 2;   // 0..60 (a)

    const float* xbase = x + ((size_t)b * S_ + s0) * D_;
    const float* wbase = W + (size_t)h * D_ * A_;

    float acc[4][4];
    #pragma unroll
    for (int i = 0; i < 4; i++)
        #pragma unroll
        for (int j = 0; j < 4; j++) acc[i][j] = 0.0f;

    for (int d0 = 0; d0 < D_; d0 += 16) {
        __syncthreads();
        // load X tile 64s x 16d, store transposed (d-major)
        float4 qv = *(const float4*)(xbase + (size_t)lrow * D_ + d0 + lc4);
        Xs[lc4 + 0][lrow] = qv.x;
        Xs[lc4 + 1][lrow] = qv.y;
        Xs[lc4 + 2][lrow] = qv.z;
        Xs[lc4 + 3][lrow] = qv.w;
        // load W tile 16d x 64a, direct
        *(float4*)&Ws[wdd][wa0] = *(const float4*)(wbase + (size_t)(d0 + wdd) * A_ + wa0);
        __syncthreads();

        #pragma unroll
        for (int kk = 0; kk < 16; kk++) {
            float4 qf = *(float4*)&Xs[kk][ty << 2];
            float4 wf = *(float4*)&Ws[kk][tx << 2];
            float qa[4] = {qf.x, qf.y, qf.z, qf.w};
            float wa[4] = {wf.x, wf.y, wf.z, wf.w};
            #pragma unroll
            for (int i = 0; i < 4; i++)
                #pragma unroll
                for (int j = 0; j < 4; j++)
                    acc[i][j] += qa[i] * wa[j];
        }
    }

    // bias + store [B,H,S,A]
    float4 bv4 = *(const float4*)(bias + h * A_ + (tx << 2));
    float bb[4] = {bv4.x, bv4.y, bv4.z, bv4.w};
    float* obase = out + (((size_t)b * H_ + h) * S_ + s0) * A_;
    #pragma unroll
    for (int i = 0; i < 4; i++) {
        float4 o;
        o.x = acc[i][0] + bb[0];
        o.y = acc[i][1] + bb[1];
        o.z = acc[i][2] + bb[2];
        o.w = acc[i][3] + bb[3];
        *(float4*)(obase + (size_t)((ty << 2) + i) * A_ + (tx << 2)) = o;
    }
}

// ---------------------------------------------------------------------------
// Flash-attention kernel: one CTA = (b, h, 64-row Q tile). No S*S materialization.
// Online softmax, O accumulated in registers (4x4 per thread).
// Grid: (S/64, B*H), block 256, dynamic smem = 4 * 64 * PADW floats.
// ---------------------------------------------------------------------------
extern __shared__ float smem_attn[];

__global__ __launch_bounds__(256) void attn_kernel(float* __restrict__ out)
{
    float* Qs = smem_attn;               // [64a][PADW] a-major: Qs[a][s]
    float* Ks = Qs + 64 * PADW;          // [64a][PADW] a-major: Ks[a][kcol]
    float* Vs = Ks + 64 * PADW;          // [64k][PADW] k-major: Vs[k][a]
    float* Ps = Vs + 64 * PADW;          // [64q][PADW] q-major: Ps[q][k]

    const int tid = threadIdx.x;
    const int ty = tid >> 4;             // q-row group
    const int tx = tid & 15;             // col group (k for S-GEMM, a for PV)
    const int qtile = blockIdx.x;
    const int bh = blockIdx.y;
    const int b = bh / H_, h = bh % H_;

    const float* qh = g_ph[0] + (((size_t)b * H_ + h) * S_) * A_;
    const float* kh = g_ph[1] + (((size_t)b * H_ + h) * S_) * A_;
    const float* vh = g_ph[2] + (((size_t)b * H_ + h) * S_) * A_;

    // Load Q tile, transposed to a-major
    #pragma unroll
    for (int r = 0; r < 4; r++) {
        int idx = tid + r * 256;
        int s = idx >> 4;
        int a0 = (idx & 15) << 2;
        float4 qv = *(const float4*)(qh + (size_t)(qtile * 64 + s) * A_ + a0);
        Qs[(a0 + 0) * PADW + s] = qv.x;
        Qs[(a0 + 1) * PADW + s] = qv.y;
        Qs[(a0 + 2) * PADW + s] = qv.z;
        Qs[(a0 + 3) * PADW + s] = qv.w;
    }

    float m[4], l[4], acc[4][4];
    #pragma unroll
    for (int i = 0; i < 4; i++) {
        m[i] = -1e30f;
        l[i] = 0.0f;
        #pragma unroll
        for (int j = 0; j < 4; j++) acc[i][j] = 0.0f;
    }

    for (int t = 0; t < S_ / 64; t++) {
        __syncthreads();   // protect Ks/Vs/Ps from previous iteration readers
        // Load K tile (transposed, a-major) and V tile (direct, k-major)
        #pragma unroll
        for (int r = 0; r < 4; r++) {
            int idx = tid + r * 256;
            int kk = idx >> 4;
            int a0 = (idx & 15) << 2;
            float4 kv = *(const float4*)(kh + (size_t)(t * 64 + kk) * A_ + a0);
            Ks[(a0 + 0) * PADW + kk] = kv.x;
            Ks[(a0 + 1) * PADW + kk] = kv.y;
            Ks[(a0 + 2) * PADW + kk] = kv.z;
            Ks[(a0 + 3) * PADW + kk] = kv.w;
            float4 vv = *(const float4*)(vh + (size_t)(t * 64 + kk) * A_ + a0);
            *(float4*)&Vs[(size_t)kk * PADW + a0] = vv;
        }
        __syncthreads();

        // S = Q * K^T for this thread's 4x4 block
        float s4[4][4];
        #pragma unroll
        for (int i = 0; i < 4; i++)
            #pragma unroll
            for (int j = 0; j < 4; j++) s4[i][j] = 0.0f;

        #pragma unroll 8
        for (int a = 0; a < 64; a++) {
            float4 qf = *(float4*)&Qs[(size_t)a * PADW + (ty << 2)];
            float4 kf = *(float4*)&Ks[(size_t)a * PADW + (tx << 2)];
            float qa[4] = {qf.x, qf.y, qf.z, qf.w};
            float ka[4] = {kf.x, kf.y, kf.z, kf.w};
            #pragma unroll
            for (int i = 0; i < 4; i++)
                #pragma unroll
                for (int j = 0; j < 4; j++)
                    s4[i][j] += qa[i] * ka[j];
        }

        // Online softmax (per q-row; row spread over 16 tx lanes -> shfl width 16)
        #pragma unroll
        for (int i = 0; i < 4; i++) {
            float mt = fmaxf(fmaxf(s4[i][0], s4[i][1]), fmaxf(s4[i][2], s4[i][3]));
            #pragma unroll
            for (int off = 8; off; off >>= 1)
                mt = fmaxf(mt, __shfl_xor_sync(0xffffffffu, mt, off, 16));
            float mn = fmaxf(m[i], mt);
            float corr = __expf(m[i] - mn);
            m[i] = mn;
            float rs = 0.0f;
            #pragma unroll
            for (int j = 0; j < 4; j++) {
                s4[i][j] = __expf(s4[i][j] - mn);
                rs += s4[i][j];
            }
            #pragma unroll
            for (int off = 8; off; off >>= 1)
                rs += __shfl_xor_sync(0xffffffffu, rs, off, 16);
            l[i] = l[i] * corr + rs;
            #pragma unroll
            for (int j = 0; j < 4; j++) acc[i][j] *= corr;
            *(float4*)&Ps[(size_t)((ty << 2) + i) * PADW + (tx << 2)] =
                make_float4(s4[i][0], s4[i][1], s4[i][2], s4[i][3]);
        }
        __syncthreads();

        // O += P @ V  (thread owns q-rows ty*4.., a-cols tx*4..)
        #pragma unroll 4
        for (int k4 = 0; k4 < 16; k4++) {
            float pfi[4][4];
            #pragma unroll
            for (int i = 0; i < 4; i++) {
                float4 pf = *(float4*)&Ps[(size_t)((ty << 2) + i) * PADW + (k4 << 2)];
                pfi[i][0] = pf.x; pfi[i][1] = pf.y; pfi[i][2] = pf.z; pfi[i][3] = pf.w;
            }
            #pragma unroll
            for (int kk = 0; kk < 4; kk++) {
                float4 vf = *(float4*)&Vs[(size_t)((k4 << 2) + kk) * PADW + (tx << 2)];
                float va0 = vf.x, va1 = vf.y, va2 = vf.z, va3 = vf.w;
                #pragma unroll
                for (int i = 0; i < 4; i++) {
                    acc[i][0] += pfi[i][kk] * va0;
                    acc[i][1] += pfi[i][kk] * va1;
                    acc[i][2] += pfi[i][kk] * va2;
                    acc[i][3] += pfi[i][kk] * va3;
                }
            }
        }
    }

    // Normalize and store: out[b, s, h*A + a]
    #pragma unroll
    for (int i = 0; i < 4; i++) {
        float inv = 1.0f / l[i];
        int s = qtile * 64 + (ty << 2) + i;
        float4 o;
        o.x = acc[i][0] * inv;
        o.y = acc[i][1] * inv;
        o.z = acc[i][2] * inv;
        o.w = acc[i][3] * inv;
        *(float4*)(out + ((size_t)b * S_ + s) * (H_ * A_) + h * A_ + (tx << 2)) = o;
    }
}

// ---------------------------------------------------------------------------
extern "C" void kernel_launch(void* const* d_in, const int* in_sizes, int n_in,
                              void* d_out, int out_size)
{
    const float* q  = (const float*)d_in[0];
    const float* k  = (const float*)d_in[1];
    const float* v  = (const float*)d_in[2];
    const float* Wq = (const float*)d_in[3];
    const float* bq = (const float*)d_in[4];
    const float* Wk = (const float*)d_in[5];
    const float* bk = (const float*)d_in[6];
    const float* Wv = (const float*)d_in[7];
    const float* bv = (const float*)d_in[8];

    const int attn_smem = 4 * 64 * PADW * (int)sizeof(float);  // 69632 B
    cudaFuncSetAttribute(attn_kernel, cudaFuncAttributeMaxDynamicSharedMemorySize, attn_smem);

    dim3 pgrid(S_ / 64, B_ * H_, 3);
    proj_kernel<<<pgrid, 256>>>(q, k, v, Wq, bq, Wk, bk, Wv, bv);

    dim3 agrid(S_ / 64, B_ * H_);
    attn_kernel<<<agrid, 256, attn_smem>>>((float*)d_out);
}